// round 2
// baseline (speedup 1.0000x reference)
#include <cuda_runtime.h>

#define NN 10000
#define EE 640000
#define FIN 128
#define NH 8
#define FOUT 16
#define NEG 0.2f
#define EPSF 1e-16f

// ---------------- scratch (static device memory; no allocation) ----------------
__device__ float g_proj[NN * FIN];      // 5.12 MB
__device__ float g_ssrc[NN * NH];
__device__ float g_stgt[NN * NH];
__device__ float g_denom[NN * NH];
__device__ float g_att[EE * NH];        // 20.5 MB unnormalized exp scores
__device__ int   g_src[EE];
__device__ int   g_tgt[EE];
__device__ int   g_count[NN];
__device__ int   g_offs[NN + 1];
__device__ int   g_cursor[NN];
__device__ int   g_ssorted[EE];         // src id per CSR slot
__device__ int   g_esorted[EE];         // original edge id per CSR slot
__device__ unsigned g_maxu;             // order-preserving-mapped float max

// ---------------- init ----------------
__global__ void k_init() {
    int i = blockIdx.x * 256 + threadIdx.x;
    if (i < NN * NH) g_denom[i] = 0.0f;
    if (i < NN) g_count[i] = 0;
    if (i == 0) g_maxu = 0u;  // below the map of -inf
}

// ---------------- edge copy (edges are int32: JAX x64 disabled) ----------------
__global__ void k_conv(const int* __restrict__ edges) {
    int e = blockIdx.x * 256 + threadIdx.x;
    if (e < EE) {
        g_src[e] = edges[e];
        g_tgt[e] = edges[EE + e];
    }
}

// ---------------- fused proj + skip GEMM (+bias) ----------------
// block: 128 threads, handles 16 node rows. thread t owns output col t of
// BOTH W_proj and W_skip (x-tile reused for 2 cols -> halves LDS traffic).
__global__ void __launch_bounds__(128) k_gemm(
    const float* __restrict__ x, const float* __restrict__ Wp,
    const float* __restrict__ Ws, const float* __restrict__ bias,
    float* __restrict__ out)
{
    __shared__ float4 xs4[16][32];
    int node0 = blockIdx.x * 16;
    int t = threadIdx.x;

    const float4* xg = (const float4*)(x + node0 * FIN);
    for (int i = t; i < 512; i += 128) xs4[i >> 5][i & 31] = xg[i];
    __syncthreads();

    float accP[16], accS[16];
#pragma unroll
    for (int n = 0; n < 16; n++) { accP[n] = 0.0f; accS[n] = 0.0f; }

    const float4* wp4 = (const float4*)(Wp + t * FIN);
    const float4* ws4 = (const float4*)(Ws + t * FIN);
    for (int k = 0; k < 32; k++) {
        float4 a = wp4[k];
        float4 b = ws4[k];
#pragma unroll
        for (int n = 0; n < 16; n++) {
            float4 xv = xs4[n][k];
            accP[n] += a.x * xv.x + a.y * xv.y + a.z * xv.z + a.w * xv.w;
            accS[n] += b.x * xv.x + b.y * xv.y + b.z * xv.z + b.w * xv.w;
        }
    }
    float bv = bias[t];
#pragma unroll
    for (int n = 0; n < 16; n++) {
        g_proj[(node0 + n) * FIN + t] = accP[n];
        out[(node0 + n) * FIN + t] = accS[n] + bv;   // skip + bias baseline
    }
}

// ---------------- per-(node,head) attention source/target scores ----------------
__global__ void k_scores(const float* __restrict__ sw_src,
                         const float* __restrict__ sw_tgt)
{
    __shared__ float sw[FIN], tw[FIN];
    int t = threadIdx.x;
    if (t < FIN) { sw[t] = sw_src[t]; tw[t] = sw_tgt[t]; }
    __syncthreads();
    int idx = blockIdx.x * 256 + t;
    if (idx >= NN * NH) return;
    int n = idx >> 3, h = idx & 7;
    const float* p = g_proj + n * FIN + h * FOUT;
    float a = 0.0f, b = 0.0f;
#pragma unroll
    for (int f = 0; f < FOUT; f++) {
        float v = p[f];
        a += v * sw[h * FOUT + f];
        b += v * tw[h * FOUT + f];
    }
    g_ssrc[idx] = a;
    g_stgt[idx] = b;
}

// ---------------- global max of leaky_relu scores ----------------
__global__ void k_max() {
    int idx = blockIdx.x * 256 + threadIdx.x;
    float s = -3.4e38f;
    if (idx < EE * NH) {
        int e = idx >> 3, h = idx & 7;
        float v = g_ssrc[g_src[e] * NH + h] + g_stgt[g_tgt[e] * NH + h];
        s = fmaxf(v, NEG * v);  // leaky_relu, slope<1
    }
#pragma unroll
    for (int o = 16; o; o >>= 1) s = fmaxf(s, __shfl_xor_sync(0xffffffffu, s, o));
    __shared__ float wsm[8];
    int lane = threadIdx.x & 31, w = threadIdx.x >> 5;
    if (lane == 0) wsm[w] = s;
    __syncthreads();
    if (threadIdx.x == 0) {
        float m = wsm[0];
#pragma unroll
        for (int i = 1; i < 8; i++) m = fmaxf(m, wsm[i]);
        unsigned u = __float_as_uint(m);
        u = (u & 0x80000000u) ? ~u : (u | 0x80000000u);  // order-preserving map
        atomicMax(&g_maxu, u);
    }
}

// ---------------- exp(score - M), store unnormalized, accumulate denom ----------------
__global__ void k_exp() {
    unsigned k = g_maxu;
    float M = __uint_as_float((k & 0x80000000u) ? (k ^ 0x80000000u) : ~k);
    int idx = blockIdx.x * 256 + threadIdx.x;
    if (idx >= EE * NH) return;
    int e = idx >> 3, h = idx & 7;
    int tg = g_tgt[e];
    float v = g_ssrc[g_src[e] * NH + h] + g_stgt[tg * NH + h];
    v = fmaxf(v, NEG * v);
    float ex = __expf(v - M);
    g_att[idx] = ex;
    atomicAdd(&g_denom[tg * NH + h], ex);
}

// ---------------- CSR build ----------------
__global__ void k_count() {
    int e = blockIdx.x * 256 + threadIdx.x;
    if (e < EE) atomicAdd(&g_count[g_tgt[e]], 1);
}

__global__ void k_scan() {  // single block, 1024 threads
    __shared__ int sh[1024];
    __shared__ int carry;
    int t = threadIdx.x;
    if (t == 0) carry = 0;
    __syncthreads();
    for (int base = 0; base < NN; base += 1024) {
        int i = base + t;
        int v = (i < NN) ? g_count[i] : 0;
        sh[t] = v;
        __syncthreads();
        for (int off = 1; off < 1024; off <<= 1) {
            int xv = 0;
            if (t >= off) xv = sh[t - off];
            __syncthreads();
            sh[t] += xv;
            __syncthreads();
        }
        int excl = sh[t] - v + carry;
        if (i < NN) { g_offs[i] = excl; g_cursor[i] = excl; }
        int total = sh[1023];
        __syncthreads();
        if (t == 0) carry += total;
        __syncthreads();
    }
    if (t == 0) g_offs[NN] = carry;
}

__global__ void k_scatter() {
    int e = blockIdx.x * 256 + threadIdx.x;
    if (e < EE) {
        int p = atomicAdd(&g_cursor[g_tgt[e]], 1);
        g_ssorted[p] = g_src[e];
        g_esorted[p] = e;
    }
}

// ---------------- aggregation: one block (128 thr) per node ----------------
__global__ void __launch_bounds__(128) k_agg(float* __restrict__ out) {
    __shared__ float inv[NH];
    __shared__ float att_s[16][NH];
    __shared__ int src_s[16];
    int n = blockIdx.x, t = threadIdx.x;
    int h = t >> 4;
    if (t < NH) inv[t] = 1.0f / (g_denom[n * NH + t] + EPSF);
    __syncthreads();

    int start = g_offs[n], end = g_offs[n + 1];
    float acc = 0.0f;
    int el = t >> 3, hh = t & 7;

    for (int base = start; base < end; base += 16) {
        int m = min(16, end - base);
        __syncthreads();
        if (el < m) {
            int eid = g_esorted[base + el];
            att_s[el][hh] = g_att[eid * NH + hh];
            if (hh == 0) src_s[el] = g_ssorted[base + el];
        }
        __syncthreads();
        int e2 = 0;
        for (; e2 + 4 <= m; e2 += 4) {  // MLP=4: batch loads before FFMAs
            float a0 = att_s[e2 + 0][h], a1 = att_s[e2 + 1][h];
            float a2 = att_s[e2 + 2][h], a3 = att_s[e2 + 3][h];
            float p0 = g_proj[src_s[e2 + 0] * FIN + t];
            float p1 = g_proj[src_s[e2 + 1] * FIN + t];
            float p2 = g_proj[src_s[e2 + 2] * FIN + t];
            float p3 = g_proj[src_s[e2 + 3] * FIN + t];
            acc += a0 * p0;
            acc += a1 * p1;
            acc += a2 * p2;
            acc += a3 * p3;
        }
        for (; e2 < m; e2++)
            acc += att_s[e2][h] * g_proj[src_s[e2] * FIN + t];
    }
    out[n * FIN + t] += acc * inv[h];
}

// ---------------- launch ----------------
extern "C" void kernel_launch(void* const* d_in, const int* in_sizes, int n_in,
                              void* d_out, int out_size)
{
    const float* x     = (const float*)d_in[0];
    const int*   edges = (const int*)d_in[1];     // int32 (JAX x64 disabled)
    const float* Wp    = (const float*)d_in[2];
    const float* Ws    = (const float*)d_in[3];
    const float* s_src = (const float*)d_in[4];
    const float* s_tgt = (const float*)d_in[5];
    const float* bias  = (const float*)d_in[6];
    float* out = (float*)d_out;

    k_init<<<(NN * NH + 255) / 256, 256>>>();
    k_conv<<<(EE + 255) / 256, 256>>>(edges);
    k_gemm<<<NN / 16, 128>>>(x, Wp, Ws, bias, out);
    k_scores<<<(NN * NH + 255) / 256, 256>>>(s_src, s_tgt);
    k_max<<<(EE * NH) / 256, 256>>>();
    k_exp<<<(EE * NH) / 256, 256>>>();
    k_count<<<(EE + 255) / 256, 256>>>();
    k_scan<<<1, 1024>>>();
    k_scatter<<<(EE + 255) / 256, 256>>>();
    k_agg<<<NN, 128>>>(out);
}

// round 3
// speedup vs baseline: 1.1897x; 1.1897x over previous
#include <cuda_runtime.h>

#define NN 10000
#define EE 640000
#define FIN 128
#define NH 8
#define FOUT 16
#define NEG 0.2f
#define EPSF 1e-16f

// ---------------- scratch (static device memory; no allocation) ----------------
__device__ float g_proj[NN * FIN];      // 5.12 MB
__device__ float g_ssrc[NN * NH];
__device__ float g_stgt[NN * NH];
__device__ float g_denom[NN * NH];
__device__ float g_att[EE * NH];        // 20.5 MB unnormalized exp scores
__device__ int   g_count[NN];
__device__ int   g_offs[NN + 1];
__device__ int   g_cursor[NN];
__device__ int   g_ssorted[EE];         // src id per CSR slot
__device__ int   g_esorted[EE];         // original edge id per CSR slot
__device__ unsigned g_maxsrc[NH];       // order-preserving-mapped per-head max
__device__ unsigned g_maxtgt[NH];

__device__ __forceinline__ unsigned f2u_ord(float f) {
    unsigned u = __float_as_uint(f);
    return (u & 0x80000000u) ? ~u : (u | 0x80000000u);
}
__device__ __forceinline__ float u2f_ord(unsigned u) {
    return __uint_as_float((u & 0x80000000u) ? (u ^ 0x80000000u) : ~u);
}

// ---------------- init ----------------
__global__ void k_init() {
    int i = blockIdx.x * 256 + threadIdx.x;
    if (i < NN * NH) g_denom[i] = 0.0f;
    if (i < NN) g_count[i] = 0;
    if (i < NH) { g_maxsrc[i] = 0u; g_maxtgt[i] = 0u; }
}

// ---------------- fused proj + skip GEMM (+bias) + attention scores ----------------
// block: 128 threads, 16 node rows. thread t owns output col t of BOTH weights.
// Epilogue: 16-lane shuffle reduction produces s_src/s_tgt per (node,head),
// plus per-head running maxima -> global atomicMax.
__global__ void __launch_bounds__(128) k_gemm(
    const float* __restrict__ x, const float* __restrict__ Wp,
    const float* __restrict__ Ws, const float* __restrict__ bias,
    const float* __restrict__ sw_src, const float* __restrict__ sw_tgt,
    float* __restrict__ out)
{
    __shared__ float4 xs4[16][32];
    int node0 = blockIdx.x * 16;
    int t = threadIdx.x;

    const float4* xg = (const float4*)(x + node0 * FIN);
    for (int i = t; i < 512; i += 128) xs4[i >> 5][i & 31] = xg[i];
    __syncthreads();

    float accP[16], accS[16];
#pragma unroll
    for (int n = 0; n < 16; n++) { accP[n] = 0.0f; accS[n] = 0.0f; }

    const float4* wp4 = (const float4*)(Wp + t * FIN);
    const float4* ws4 = (const float4*)(Ws + t * FIN);
    for (int k = 0; k < 32; k++) {
        float4 a = wp4[k];
        float4 b = ws4[k];
#pragma unroll
        for (int n = 0; n < 16; n++) {
            float4 xv = xs4[n][k];
            accP[n] += a.x * xv.x + a.y * xv.y + a.z * xv.z + a.w * xv.w;
            accS[n] += b.x * xv.x + b.y * xv.y + b.z * xv.z + b.w * xv.w;
        }
    }
    float bv = bias[t];
#pragma unroll
    for (int n = 0; n < 16; n++) {
        g_proj[(node0 + n) * FIN + t] = accP[n];
        out[(node0 + n) * FIN + t] = accS[n] + bv;   // skip + bias baseline
    }

    // ---- epilogue: per-(node,head) scores via 16-lane shuffle reduction ----
    float swv = sw_src[t], twv = sw_tgt[t];
    int h = t >> 4;
    bool leader = (t & 15) == 0;
    float msrc = -3.4e38f, mtgt = -3.4e38f;
#pragma unroll
    for (int n = 0; n < 16; n++) {
        float ps = accP[n] * swv;
        float pt = accP[n] * twv;
#pragma unroll
        for (int o = 8; o; o >>= 1) {
            ps += __shfl_down_sync(0xffffffffu, ps, o, 16);
            pt += __shfl_down_sync(0xffffffffu, pt, o, 16);
        }
        if (leader) {
            g_ssrc[(node0 + n) * NH + h] = ps;
            g_stgt[(node0 + n) * NH + h] = pt;
            msrc = fmaxf(msrc, ps);
            mtgt = fmaxf(mtgt, pt);
        }
    }
    if (leader) {
        atomicMax(&g_maxsrc[h], f2u_ord(msrc));
        atomicMax(&g_maxtgt[h], f2u_ord(mtgt));
    }
}

// ---------------- per-edge: leaky_relu + exp, denom red.v4, CSR count ----------------
__global__ void k_exp(const int* __restrict__ edges) {
    int e = blockIdx.x * 256 + threadIdx.x;
    if (e >= EE) return;
    int sdx = edges[e];
    int tg  = edges[EE + e];

    // per-head shift constants (upper bound of edge max; softmax shift-invariant)
    float C[NH];
#pragma unroll
    for (int h = 0; h < NH; h++) {
        float c = u2f_ord(g_maxsrc[h]) + u2f_ord(g_maxtgt[h]);
        C[h] = fmaxf(c, NEG * c);
    }

    const float4* a4 = (const float4*)(g_ssrc + sdx * NH);
    const float4* b4 = (const float4*)(g_stgt + tg * NH);
    float4 a0 = a4[0], a1 = a4[1];
    float4 b0 = b4[0], b1 = b4[1];

    float v[NH] = { a0.x + b0.x, a0.y + b0.y, a0.z + b0.z, a0.w + b0.w,
                    a1.x + b1.x, a1.y + b1.y, a1.z + b1.z, a1.w + b1.w };
    float ex[NH];
#pragma unroll
    for (int h = 0; h < NH; h++) {
        float lr = fmaxf(v[h], NEG * v[h]);
        ex[h] = __expf(lr - C[h]);
    }

    float4* att4 = (float4*)(g_att + (size_t)e * NH);
    att4[0] = make_float4(ex[0], ex[1], ex[2], ex[3]);
    att4[1] = make_float4(ex[4], ex[5], ex[6], ex[7]);

    float* dn = g_denom + tg * NH;
    asm volatile("red.global.add.v4.f32 [%0], {%1,%2,%3,%4};"
                 :: "l"(dn), "f"(ex[0]), "f"(ex[1]), "f"(ex[2]), "f"(ex[3]) : "memory");
    asm volatile("red.global.add.v4.f32 [%0], {%1,%2,%3,%4};"
                 :: "l"(dn + 4), "f"(ex[4]), "f"(ex[5]), "f"(ex[6]), "f"(ex[7]) : "memory");

    atomicAdd(&g_count[tg], 1);   // fused CSR count
}

// ---------------- CSR scan (single block) ----------------
__global__ void k_scan() {
    __shared__ int sh[1024];
    __shared__ int carry;
    int t = threadIdx.x;
    if (t == 0) carry = 0;
    __syncthreads();
    for (int base = 0; base < NN; base += 1024) {
        int i = base + t;
        int v = (i < NN) ? g_count[i] : 0;
        sh[t] = v;
        __syncthreads();
        for (int off = 1; off < 1024; off <<= 1) {
            int xv = 0;
            if (t >= off) xv = sh[t - off];
            __syncthreads();
            sh[t] += xv;
            __syncthreads();
        }
        int excl = sh[t] - v + carry;
        if (i < NN) { g_offs[i] = excl; g_cursor[i] = excl; }
        int total = sh[1023];
        __syncthreads();
        if (t == 0) carry += total;
        __syncthreads();
    }
    if (t == 0) g_offs[NN] = carry;
}

__global__ void k_scatter(const int* __restrict__ edges) {
    int e = blockIdx.x * 256 + threadIdx.x;
    if (e < EE) {
        int p = atomicAdd(&g_cursor[edges[EE + e]], 1);
        g_ssorted[p] = edges[e];
        g_esorted[p] = e;
    }
}

// ---------------- aggregation: one block (128 thr) per node, tile=32 edges ----------------
__global__ void __launch_bounds__(128) k_agg(float* __restrict__ out) {
    __shared__ float inv[NH];
    __shared__ float att_s[32][NH];
    __shared__ int src_s[32];
    int n = blockIdx.x, t = threadIdx.x;
    int h = t >> 4;
    if (t < NH) inv[t] = 1.0f / (g_denom[n * NH + t] + EPSF);
    __syncthreads();

    int start = g_offs[n], end = g_offs[n + 1];
    float acc = 0.0f;
    int hh = t & 7;

    for (int base = start; base < end; base += 32) {
        int m = min(32, end - base);
        __syncthreads();
#pragma unroll
        for (int j = 0; j < 2; j++) {
            int slot = (t >> 3) + j * 16;
            if (slot < m) {
                int eid = g_esorted[base + slot];
                att_s[slot][hh] = g_att[(size_t)eid * NH + hh];
                if (hh == 0) src_s[slot] = g_ssorted[base + slot];
            }
        }
        __syncthreads();
        int e2 = 0;
        for (; e2 + 4 <= m; e2 += 4) {  // MLP=4: batch loads before FFMAs
            float a0 = att_s[e2 + 0][h], a1 = att_s[e2 + 1][h];
            float a2 = att_s[e2 + 2][h], a3 = att_s[e2 + 3][h];
            float p0 = g_proj[src_s[e2 + 0] * FIN + t];
            float p1 = g_proj[src_s[e2 + 1] * FIN + t];
            float p2 = g_proj[src_s[e2 + 2] * FIN + t];
            float p3 = g_proj[src_s[e2 + 3] * FIN + t];
            acc += a0 * p0;
            acc += a1 * p1;
            acc += a2 * p2;
            acc += a3 * p3;
        }
        for (; e2 < m; e2++)
            acc += att_s[e2][h] * g_proj[src_s[e2] * FIN + t];
    }
    out[n * FIN + t] += acc * inv[h];
}

// ---------------- launch ----------------
extern "C" void kernel_launch(void* const* d_in, const int* in_sizes, int n_in,
                              void* d_out, int out_size)
{
    const float* x     = (const float*)d_in[0];
    const int*   edges = (const int*)d_in[1];     // int32 (JAX x64 disabled)
    const float* Wp    = (const float*)d_in[2];
    const float* Ws    = (const float*)d_in[3];
    const float* s_src = (const float*)d_in[4];
    const float* s_tgt = (const float*)d_in[5];
    const float* bias  = (const float*)d_in[6];
    float* out = (float*)d_out;

    k_init<<<(NN * NH + 255) / 256, 256>>>();
    k_gemm<<<NN / 16, 128>>>(x, Wp, Ws, bias, s_src, s_tgt, out);
    k_exp<<<(EE + 255) / 256, 256>>>(edges);
    k_scan<<<1, 1024>>>();
    k_scatter<<<(EE + 255) / 256, 256>>>(edges);
    k_agg<<<NN, 128>>>(out);
}

// round 4
// speedup vs baseline: 1.2699x; 1.0674x over previous
#include <cuda_runtime.h>

#define NN 10000
#define EE 640000
#define FIN 128
#define NH 8
#define FOUT 16
#define NEG 0.2f
#define EPSF 1e-16f

// ---------------- scratch (static device memory; no allocation) ----------------
__device__ float g_proj[NN * FIN];      // 5.12 MB
__device__ float g_ssrc[NN * NH];
__device__ float g_stgt[NN * NH];
__device__ float g_denom[NN * NH];
__device__ float g_att[EE * NH];        // 20.5 MB, CSR-ordered unnormalized exp
__device__ int   g_count[NN];
__device__ int   g_offs[NN + 1];
__device__ int   g_cursor[NN];
__device__ int   g_ssorted[EE];         // src id per CSR slot
__device__ unsigned g_maxsrc[NH];       // order-preserving-mapped per-head max
__device__ unsigned g_maxtgt[NH];
__device__ float g_C[NH];               // softmax shift constants

__device__ __forceinline__ unsigned f2u_ord(float f) {
    unsigned u = __float_as_uint(f);
    return (u & 0x80000000u) ? ~u : (u | 0x80000000u);
}
__device__ __forceinline__ float u2f_ord(unsigned u) {
    return __uint_as_float((u & 0x80000000u) ? (u ^ 0x80000000u) : ~u);
}

// ---------------- init ----------------
__global__ void k_init() {
    int i = blockIdx.x * 256 + threadIdx.x;
    if (i < NN * NH) g_denom[i] = 0.0f;
    if (i < NN) g_count[i] = 0;
    if (i < NH) { g_maxsrc[i] = 0u; g_maxtgt[i] = 0u; }
}

// ---------------- per-target degree count ----------------
__global__ void k_count(const int* __restrict__ edges) {
    int e = blockIdx.x * 256 + threadIdx.x;
    if (e < EE) atomicAdd(&g_count[edges[EE + e]], 1);
}

// ---------------- fused proj + skip GEMM (+bias) + attention scores ----------------
__global__ void __launch_bounds__(128) k_gemm(
    const float* __restrict__ x, const float* __restrict__ Wp,
    const float* __restrict__ Ws, const float* __restrict__ bias,
    const float* __restrict__ sw_src, const float* __restrict__ sw_tgt,
    float* __restrict__ out)
{
    __shared__ float4 xs4[16][32];
    int node0 = blockIdx.x * 16;
    int t = threadIdx.x;

    const float4* xg = (const float4*)(x + node0 * FIN);
    for (int i = t; i < 512; i += 128) xs4[i >> 5][i & 31] = xg[i];
    __syncthreads();

    float accP[16], accS[16];
#pragma unroll
    for (int n = 0; n < 16; n++) { accP[n] = 0.0f; accS[n] = 0.0f; }

    const float4* wp4 = (const float4*)(Wp + t * FIN);
    const float4* ws4 = (const float4*)(Ws + t * FIN);
    for (int k = 0; k < 32; k++) {
        float4 a = wp4[k];
        float4 b = ws4[k];
#pragma unroll
        for (int n = 0; n < 16; n++) {
            float4 xv = xs4[n][k];
            accP[n] += a.x * xv.x + a.y * xv.y + a.z * xv.z + a.w * xv.w;
            accS[n] += b.x * xv.x + b.y * xv.y + b.z * xv.z + b.w * xv.w;
        }
    }
    float bv = bias[t];
#pragma unroll
    for (int n = 0; n < 16; n++) {
        g_proj[(node0 + n) * FIN + t] = accP[n];
        out[(node0 + n) * FIN + t] = accS[n] + bv;   // skip + bias baseline
    }

    // ---- epilogue: per-(node,head) scores via 16-lane shuffle reduction ----
    float swv = sw_src[t], twv = sw_tgt[t];
    int h = t >> 4;
    bool leader = (t & 15) == 0;
    float msrc = -3.4e38f, mtgt = -3.4e38f;
#pragma unroll
    for (int n = 0; n < 16; n++) {
        float ps = accP[n] * swv;
        float pt = accP[n] * twv;
#pragma unroll
        for (int o = 8; o; o >>= 1) {
            ps += __shfl_down_sync(0xffffffffu, ps, o, 16);
            pt += __shfl_down_sync(0xffffffffu, pt, o, 16);
        }
        if (leader) {
            g_ssrc[(node0 + n) * NH + h] = ps;
            g_stgt[(node0 + n) * NH + h] = pt;
            msrc = fmaxf(msrc, ps);
            mtgt = fmaxf(mtgt, pt);
        }
    }
    if (leader) {
        atomicMax(&g_maxsrc[h], f2u_ord(msrc));
        atomicMax(&g_maxtgt[h], f2u_ord(mtgt));
    }
}

// ---------------- CSR scan: single-pass warp-shuffle scan + C[] constants ----------------
__global__ void __launch_bounds__(1024) k_scan() {
    const int PER = 10;                 // 1024 * 10 >= NN
    int t = threadIdx.x;
    int base = t * PER;
    int loc[PER];
    int sum = 0;
#pragma unroll
    for (int i = 0; i < PER; i++) {
        int idx = base + i;
        int v = (idx < NN) ? g_count[idx] : 0;
        loc[i] = sum;
        sum += v;
    }
    int lane = t & 31, w = t >> 5;
    int s = sum;
#pragma unroll
    for (int o = 1; o < 32; o <<= 1) {
        int y = __shfl_up_sync(0xffffffffu, s, o);
        if (lane >= o) s += y;
    }
    __shared__ int wt[32];
    if (lane == 31) wt[w] = s;
    __syncthreads();
    if (w == 0) {
        int v = wt[lane];
        int s2 = v;
#pragma unroll
        for (int o = 1; o < 32; o <<= 1) {
            int y = __shfl_up_sync(0xffffffffu, s2, o);
            if (lane >= o) s2 += y;
        }
        wt[lane] = s2 - v;
    }
    __syncthreads();
    int off = (s - sum) + wt[w];
#pragma unroll
    for (int i = 0; i < PER; i++) {
        int idx = base + i;
        if (idx < NN) {
            int o = off + loc[i];
            g_offs[idx] = o;
            g_cursor[idx] = o;
        }
    }
    if (t == 1023) g_offs[NN] = off + sum;

    // softmax shift constants (upper bound of edge max; shift-invariant)
    if (t < NH) {
        float c = u2f_ord(g_maxsrc[t]) + u2f_ord(g_maxtgt[t]);
        g_C[t] = fmaxf(c, NEG * c);
    }
}

// ---------------- per-edge: exp + CSR scatter + denom red.v4 ----------------
__global__ void k_exp(const int* __restrict__ edges) {
    int e = blockIdx.x * 256 + threadIdx.x;
    if (e >= EE) return;
    int sdx = edges[e];
    int tg  = edges[EE + e];

    const float4* c4 = (const float4*)g_C;
    float4 C0 = c4[0], C1 = c4[1];
    const float4* a4 = (const float4*)(g_ssrc + sdx * NH);
    const float4* b4 = (const float4*)(g_stgt + tg * NH);
    float4 a0 = a4[0], a1 = a4[1];
    float4 b0 = b4[0], b1 = b4[1];

    float v[NH] = { a0.x + b0.x, a0.y + b0.y, a0.z + b0.z, a0.w + b0.w,
                    a1.x + b1.x, a1.y + b1.y, a1.z + b1.z, a1.w + b1.w };
    float Cv[NH] = { C0.x, C0.y, C0.z, C0.w, C1.x, C1.y, C1.z, C1.w };
    float ex[NH];
#pragma unroll
    for (int h = 0; h < NH; h++) {
        float lr = fmaxf(v[h], NEG * v[h]);
        ex[h] = __expf(lr - Cv[h]);
    }

    // CSR slot (order within a segment is arbitrary; sums are commutative)
    int p = atomicAdd(&g_cursor[tg], 1);
    g_ssorted[p] = sdx;
    float4* att4 = (float4*)(g_att + (size_t)p * NH);
    att4[0] = make_float4(ex[0], ex[1], ex[2], ex[3]);
    att4[1] = make_float4(ex[4], ex[5], ex[6], ex[7]);

    float* dn = g_denom + tg * NH;
    asm volatile("red.global.add.v4.f32 [%0], {%1,%2,%3,%4};"
                 :: "l"(dn), "f"(ex[0]), "f"(ex[1]), "f"(ex[2]), "f"(ex[3]) : "memory");
    asm volatile("red.global.add.v4.f32 [%0], {%1,%2,%3,%4};"
                 :: "l"(dn + 4), "f"(ex[4]), "f"(ex[5]), "f"(ex[6]), "f"(ex[7]) : "memory");
}

// ---------------- aggregation: one block (128 thr) per node, tile=32 edges ----------------
__global__ void __launch_bounds__(128) k_agg(float* __restrict__ out) {
    __shared__ float inv[NH];
    __shared__ float att_s[32][NH];
    __shared__ int src_s[32];
    int n = blockIdx.x, t = threadIdx.x;
    int h = t >> 4;
    if (t < NH) inv[t] = 1.0f / (g_denom[n * NH + t] + EPSF);
    __syncthreads();

    int start = g_offs[n], end = g_offs[n + 1];
    float acc = 0.0f;

    for (int base = start; base < end; base += 32) {
        int m = min(32, end - base);
        __syncthreads();
        // att is CSR-contiguous now: 256 consecutive floats, fully coalesced
#pragma unroll
        for (int j = 0; j < 2; j++) {
            int idx = t + j * 128;            // [0,256)
            int slot = idx >> 3, hh = idx & 7;
            if (slot < m)
                att_s[slot][hh] = g_att[(size_t)(base + slot) * NH + hh];
        }
        if (t < m) src_s[t] = g_ssorted[base + t];
        __syncthreads();
        int e2 = 0;
        for (; e2 + 4 <= m; e2 += 4) {  // MLP=4: batch loads before FFMAs
            float a0 = att_s[e2 + 0][h], a1 = att_s[e2 + 1][h];
            float a2 = att_s[e2 + 2][h], a3 = att_s[e2 + 3][h];
            float p0 = g_proj[src_s[e2 + 0] * FIN + t];
            float p1 = g_proj[src_s[e2 + 1] * FIN + t];
            float p2 = g_proj[src_s[e2 + 2] * FIN + t];
            float p3 = g_proj[src_s[e2 + 3] * FIN + t];
            acc += a0 * p0;
            acc += a1 * p1;
            acc += a2 * p2;
            acc += a3 * p3;
        }
        for (; e2 < m; e2++)
            acc += att_s[e2][h] * g_proj[src_s[e2] * FIN + t];
    }
    out[n * FIN + t] += acc * inv[h];
}

// ---------------- launch ----------------
extern "C" void kernel_launch(void* const* d_in, const int* in_sizes, int n_in,
                              void* d_out, int out_size)
{
    const float* x     = (const float*)d_in[0];
    const int*   edges = (const int*)d_in[1];     // int32 (JAX x64 disabled)
    const float* Wp    = (const float*)d_in[2];
    const float* Ws    = (const float*)d_in[3];
    const float* s_src = (const float*)d_in[4];
    const float* s_tgt = (const float*)d_in[5];
    const float* bias  = (const float*)d_in[6];
    float* out = (float*)d_out;

    k_init<<<(NN * NH + 255) / 256, 256>>>();
    k_count<<<(EE + 255) / 256, 256>>>(edges);
    k_gemm<<<NN / 16, 128>>>(x, Wp, Ws, bias, s_src, s_tgt, out);
    k_scan<<<1, 1024>>>();
    k_exp<<<(EE + 255) / 256, 256>>>(edges);
    k_agg<<<NN, 128>>>(out);
}

// round 5
// speedup vs baseline: 1.4034x; 1.1051x over previous
#include <cuda_runtime.h>

#define NN 10000
#define EE 640000
#define FIN 128
#define NH 8
#define FOUT 16
#define NEG 0.2f
#define EPSF 1e-16f

#define GEMM_BLOCKS 313          // ceil(10000/32)
#define COUNT_BLOCKS ((EE + 255) / 256)

// ---------------- scratch (static device memory; zero-initialized at load) -----
__device__ float g_proj[NN * FIN];      // 5.12 MB
__device__ float g_ssrc[NN * NH];
__device__ float g_stgt[NN * NH];
__device__ float g_denom[NN * NH];      // zeroed at end of k_agg
__device__ float g_att[EE * NH];        // 20.5 MB, CSR-ordered unnormalized exp
__device__ int   g_count[NN];           // zeroed at end of k_agg
__device__ int   g_offs[NN + 1];
__device__ int   g_cursor[NN];
__device__ int   g_ssorted[EE];         // src id per CSR slot
__device__ unsigned g_maxsrc[NH];       // zeroed at end of k_agg
__device__ unsigned g_maxtgt[NH];
__device__ float g_C[NH];               // softmax shift constants

__device__ __forceinline__ unsigned f2u_ord(float f) {
    unsigned u = __float_as_uint(f);
    return (u & 0x80000000u) ? ~u : (u | 0x80000000u);
}
__device__ __forceinline__ float u2f_ord(unsigned u) {
    return __uint_as_float((u & 0x80000000u) ? (u ^ 0x80000000u) : ~u);
}

// ---------------- fused: proj+skip GEMM (+bias,+scores)  ||  edge counting -----
// blocks [0, GEMM_BLOCKS): 256 threads = two independent 128-thread sub-blocks,
// each handling 16 node rows (thread tt owns output col tt of BOTH weights).
// blocks [GEMM_BLOCKS, +COUNT_BLOCKS): per-target degree count (backfills SMs).
__global__ void __launch_bounds__(256) k_fused(
    const float* __restrict__ x, const float* __restrict__ Wp,
    const float* __restrict__ Ws, const float* __restrict__ bias,
    const float* __restrict__ sw_src, const float* __restrict__ sw_tgt,
    const int* __restrict__ edges, float* __restrict__ out)
{
    __shared__ float4 xs4[2][16][32];   // 16 KB
    int t = threadIdx.x;

    if (blockIdx.x >= GEMM_BLOCKS) {
        int e = (blockIdx.x - GEMM_BLOCKS) * 256 + t;
        if (e < EE) atomicAdd(&g_count[edges[EE + e]], 1);
        return;
    }

    int sb = t >> 7;                    // sub-block 0/1
    int tt = t & 127;
    int node0 = blockIdx.x * 32 + sb * 16;
    if (node0 >= NN) return;            // tail half-block

    const float4* xg = (const float4*)(x + node0 * FIN);
    for (int i = tt; i < 512; i += 128) xs4[sb][i >> 5][i & 31] = xg[i];
    __syncwarp();
    __syncthreads();

    float accP[16], accS[16];
#pragma unroll
    for (int n = 0; n < 16; n++) { accP[n] = 0.0f; accS[n] = 0.0f; }

    const float4* wp4 = (const float4*)(Wp + tt * FIN);
    const float4* ws4 = (const float4*)(Ws + tt * FIN);
    for (int k = 0; k < 32; k++) {
        float4 a = wp4[k];
        float4 b = ws4[k];
#pragma unroll
        for (int n = 0; n < 16; n++) {
            float4 xv = xs4[sb][n][k];
            accP[n] += a.x * xv.x + a.y * xv.y + a.z * xv.z + a.w * xv.w;
            accS[n] += b.x * xv.x + b.y * xv.y + b.z * xv.z + b.w * xv.w;
        }
    }
    float bv = bias[tt];
#pragma unroll
    for (int n = 0; n < 16; n++) {
        g_proj[(node0 + n) * FIN + tt] = accP[n];
        out[(node0 + n) * FIN + tt] = accS[n] + bv;   // skip + bias baseline
    }

    // ---- epilogue: per-(node,head) scores via 16-lane shuffle reduction ----
    float swv = sw_src[tt], twv = sw_tgt[tt];
    int h = tt >> 4;
    bool leader = (tt & 15) == 0;
    float msrc = -3.4e38f, mtgt = -3.4e38f;
#pragma unroll
    for (int n = 0; n < 16; n++) {
        float ps = accP[n] * swv;
        float pt = accP[n] * twv;
#pragma unroll
        for (int o = 8; o; o >>= 1) {
            ps += __shfl_down_sync(0xffffffffu, ps, o, 16);
            pt += __shfl_down_sync(0xffffffffu, pt, o, 16);
        }
        if (leader) {
            g_ssrc[(node0 + n) * NH + h] = ps;
            g_stgt[(node0 + n) * NH + h] = pt;
            msrc = fmaxf(msrc, ps);
            mtgt = fmaxf(mtgt, pt);
        }
    }
    if (leader) {
        atomicMax(&g_maxsrc[h], f2u_ord(msrc));
        atomicMax(&g_maxtgt[h], f2u_ord(mtgt));
    }
}

// ---------------- CSR scan: coalesced smem staging + warp-shuffle scan ---------
__global__ void __launch_bounds__(1024) k_scan() {
    const int PER = 10;                 // 1024 * 10 >= NN
    __shared__ int cs[NN];              // 40 KB, coalesced staging
    __shared__ int wt[32];
    int t = threadIdx.x;

    for (int i = t; i < NN; i += 1024) cs[i] = g_count[i];   // coalesced, MLP=10
    __syncthreads();

    int base = t * PER;
    int loc[PER];
    int sum = 0;
#pragma unroll
    for (int i = 0; i < PER; i++) {
        int idx = base + i;
        int v = (idx < NN) ? cs[idx] : 0;
        loc[i] = sum;
        sum += v;
    }
    int lane = t & 31, w = t >> 5;
    int s = sum;
#pragma unroll
    for (int o = 1; o < 32; o <<= 1) {
        int y = __shfl_up_sync(0xffffffffu, s, o);
        if (lane >= o) s += y;
    }
    if (lane == 31) wt[w] = s;
    __syncthreads();
    if (w == 0) {
        int v = wt[lane];
        int s2 = v;
#pragma unroll
        for (int o = 1; o < 32; o <<= 1) {
            int y = __shfl_up_sync(0xffffffffu, s2, o);
            if (lane >= o) s2 += y;
        }
        wt[lane] = s2 - v;
    }
    __syncthreads();
    int off = (s - sum) + wt[w];
#pragma unroll
    for (int i = 0; i < PER; i++) {
        int idx = base + i;
        if (idx < NN) cs[idx] = off + loc[i];
    }
    __syncthreads();
    for (int i = t; i < NN; i += 1024) {   // coalesced write-out
        int o = cs[i];
        g_offs[i] = o;
        g_cursor[i] = o;
    }
    if (t == 1023) g_offs[NN] = off + sum;

    // softmax shift constants (upper bound of edge max; shift-invariant)
    if (t < NH) {
        float c = u2f_ord(g_maxsrc[t]) + u2f_ord(g_maxtgt[t]);
        g_C[t] = fmaxf(c, NEG * c);
    }
}

// ---------------- per-edge: exp + CSR scatter + denom red.v4 ----------------
__global__ void k_exp(const int* __restrict__ edges) {
    int e = blockIdx.x * 256 + threadIdx.x;
    if (e >= EE) return;
    int sdx = edges[e];
    int tg  = edges[EE + e];

    const float4* c4 = (const float4*)g_C;
    float4 C0 = c4[0], C1 = c4[1];
    const float4* a4 = (const float4*)(g_ssrc + sdx * NH);
    const float4* b4 = (const float4*)(g_stgt + tg * NH);
    float4 a0 = a4[0], a1 = a4[1];
    float4 b0 = b4[0], b1 = b4[1];

    float v[NH] = { a0.x + b0.x, a0.y + b0.y, a0.z + b0.z, a0.w + b0.w,
                    a1.x + b1.x, a1.y + b1.y, a1.z + b1.z, a1.w + b1.w };
    float Cv[NH] = { C0.x, C0.y, C0.z, C0.w, C1.x, C1.y, C1.z, C1.w };
    float ex[NH];
#pragma unroll
    for (int h = 0; h < NH; h++) {
        float lr = fmaxf(v[h], NEG * v[h]);
        ex[h] = __expf(lr - Cv[h]);
    }

    // CSR slot (order within a segment is arbitrary; sums are commutative)
    int p = atomicAdd(&g_cursor[tg], 1);
    g_ssorted[p] = sdx;
    float4* att4 = (float4*)(g_att + (size_t)p * NH);
    att4[0] = make_float4(ex[0], ex[1], ex[2], ex[3]);
    att4[1] = make_float4(ex[4], ex[5], ex[6], ex[7]);

    float* dn = g_denom + tg * NH;
    asm volatile("red.global.add.v4.f32 [%0], {%1,%2,%3,%4};"
                 :: "l"(dn), "f"(ex[0]), "f"(ex[1]), "f"(ex[2]), "f"(ex[3]) : "memory");
    asm volatile("red.global.add.v4.f32 [%0], {%1,%2,%3,%4};"
                 :: "l"(dn + 4), "f"(ex[4]), "f"(ex[5]), "f"(ex[6]), "f"(ex[7]) : "memory");
}

// ---------------- aggregation: one block (128 thr) per node + state re-zero ----
__global__ void __launch_bounds__(128) k_agg(float* __restrict__ out) {
    __shared__ float inv[NH];
    __shared__ float att_s[32][NH];
    __shared__ int src_s[32];
    int n = blockIdx.x, t = threadIdx.x;
    int h = t >> 4;
    if (t < NH) {
        inv[t] = 1.0f / (g_denom[n * NH + t] + EPSF);
        g_denom[n * NH + t] = 0.0f;            // re-zero for next replay
    }
    if (t == 8) g_count[n] = 0;                // re-zero for next replay
    if (n == 0 && t >= 16 && t < 24) g_maxsrc[t - 16] = 0u;
    if (n == 0 && t >= 24 && t < 32) g_maxtgt[t - 24] = 0u;
    __syncthreads();

    int start = g_offs[n], end = g_offs[n + 1];
    float acc = 0.0f;

    for (int base = start; base < end; base += 32) {
        int m = min(32, end - base);
        __syncthreads();
        // att is CSR-contiguous: 256 consecutive floats, fully coalesced
#pragma unroll
        for (int j = 0; j < 2; j++) {
            int idx = t + j * 128;            // [0,256)
            int slot = idx >> 3, hh = idx & 7;
            if (slot < m)
                att_s[slot][hh] = g_att[(size_t)(base + slot) * NH + hh];
        }
        if (t < m) src_s[t] = g_ssorted[base + t];
        __syncthreads();
        int e2 = 0;
        for (; e2 + 8 <= m; e2 += 8) {  // MLP=8: batch loads before FFMAs
            float a0 = att_s[e2 + 0][h], a1 = att_s[e2 + 1][h];
            float a2 = att_s[e2 + 2][h], a3 = att_s[e2 + 3][h];
            float a4 = att_s[e2 + 4][h], a5 = att_s[e2 + 5][h];
            float a6 = att_s[e2 + 6][h], a7 = att_s[e2 + 7][h];
            float p0 = g_proj[src_s[e2 + 0] * FIN + t];
            float p1 = g_proj[src_s[e2 + 1] * FIN + t];
            float p2 = g_proj[src_s[e2 + 2] * FIN + t];
            float p3 = g_proj[src_s[e2 + 3] * FIN + t];
            float p4 = g_proj[src_s[e2 + 4] * FIN + t];
            float p5 = g_proj[src_s[e2 + 5] * FIN + t];
            float p6 = g_proj[src_s[e2 + 6] * FIN + t];
            float p7 = g_proj[src_s[e2 + 7] * FIN + t];
            acc += a0 * p0; acc += a1 * p1; acc += a2 * p2; acc += a3 * p3;
            acc += a4 * p4; acc += a5 * p5; acc += a6 * p6; acc += a7 * p7;
        }
        for (; e2 < m; e2++)
            acc += att_s[e2][h] * g_proj[src_s[e2] * FIN + t];
    }
    out[n * FIN + t] += acc * inv[h];
}

// ---------------- launch ----------------
extern "C" void kernel_launch(void* const* d_in, const int* in_sizes, int n_in,
                              void* d_out, int out_size)
{
    const float* x     = (const float*)d_in[0];
    const int*   edges = (const int*)d_in[1];     // int32 (JAX x64 disabled)
    const float* Wp    = (const float*)d_in[2];
    const float* Ws    = (const float*)d_in[3];
    const float* s_src = (const float*)d_in[4];
    const float* s_tgt = (const float*)d_in[5];
    const float* bias  = (const float*)d_in[6];
    float* out = (float*)d_out;

    k_fused<<<GEMM_BLOCKS + COUNT_BLOCKS, 256>>>(x, Wp, Ws, bias, s_src, s_tgt, edges, out);
    k_scan<<<1, 1024>>>();
    k_exp<<<(EE + 255) / 256, 256>>>(edges);
    k_agg<<<NN, 128>>>(out);
}

// round 8
// speedup vs baseline: 1.6402x; 1.1687x over previous
#include <cuda_runtime.h>

#define NN 10000
#define EE 640000
#define FIN 128
#define NH 8
#define FOUT 16
#define NEG 0.2f
#define EPSF 1e-16f

#define GEMM_BLOCKS 313          // ceil(10000/32)
#define COUNT_BLOCKS ((EE + 255) / 256)

// ---------------- scratch (static device memory; zero-initialized at load) -----
__device__ float g_proj[NN * FIN];      // 5.12 MB
__device__ float g_ssrc[NN * NH];
__device__ float g_stgt[NN * NH];
__device__ int   g_count[NN];           // zeroed at end of k_agg
__device__ int   g_offs[NN + 1];
__device__ int   g_cursor[NN];
__device__ int   g_ssorted[EE];         // src id per CSR slot
__device__ unsigned g_maxsrc[NH];       // zeroed at end of k_agg
__device__ unsigned g_maxtgt[NH];
__device__ float g_C[NH];               // softmax shift constants

__device__ __forceinline__ unsigned f2u_ord(float f) {
    unsigned u = __float_as_uint(f);
    return (u & 0x80000000u) ? ~u : (u | 0x80000000u);
}
__device__ __forceinline__ float u2f_ord(unsigned u) {
    return __uint_as_float((u & 0x80000000u) ? (u ^ 0x80000000u) : ~u);
}

// ---------------- fused: proj+skip GEMM (+bias,+scores)  ||  edge counting -----
__global__ void __launch_bounds__(256) k_fused(
    const float* __restrict__ x, const float* __restrict__ Wp,
    const float* __restrict__ Ws, const float* __restrict__ bias,
    const float* __restrict__ sw_src, const float* __restrict__ sw_tgt,
    const int* __restrict__ edges, float* __restrict__ out)
{
    __shared__ float4 xs4[2][16][32];   // 16 KB
    int t = threadIdx.x;

    if (blockIdx.x >= GEMM_BLOCKS) {
        int e = (blockIdx.x - GEMM_BLOCKS) * 256 + t;
        if (e < EE) atomicAdd(&g_count[edges[EE + e]], 1);
        return;
    }

    int sb = t >> 7;                    // sub-block 0/1
    int tt = t & 127;
    int node0 = blockIdx.x * 32 + sb * 16;
    if (node0 >= NN) return;            // tail half-block

    const float4* xg = (const float4*)(x + node0 * FIN);
    for (int i = tt; i < 512; i += 128) xs4[sb][i >> 5][i & 31] = xg[i];
    __syncwarp();
    __syncthreads();

    float accP[16], accS[16];
#pragma unroll
    for (int n = 0; n < 16; n++) { accP[n] = 0.0f; accS[n] = 0.0f; }

    const float4* wp4 = (const float4*)(Wp + tt * FIN);
    const float4* ws4 = (const float4*)(Ws + tt * FIN);
    for (int k = 0; k < 32; k++) {
        float4 a = wp4[k];
        float4 b = ws4[k];
#pragma unroll
        for (int n = 0; n < 16; n++) {
            float4 xv = xs4[sb][n][k];
            accP[n] += a.x * xv.x + a.y * xv.y + a.z * xv.z + a.w * xv.w;
            accS[n] += b.x * xv.x + b.y * xv.y + b.z * xv.z + b.w * xv.w;
        }
    }
    float bv = bias[tt];
#pragma unroll
    for (int n = 0; n < 16; n++) {
        g_proj[(node0 + n) * FIN + tt] = accP[n];
        out[(node0 + n) * FIN + tt] = accS[n] + bv;   // skip + bias baseline
    }

    // ---- epilogue: per-(node,head) scores via 16-lane shuffle reduction ----
    float swv = sw_src[tt], twv = sw_tgt[tt];
    int h = tt >> 4;
    bool leader = (tt & 15) == 0;
    float msrc = -3.4e38f, mtgt = -3.4e38f;
#pragma unroll
    for (int n = 0; n < 16; n++) {
        float ps = accP[n] * swv;
        float pt = accP[n] * twv;
#pragma unroll
        for (int o = 8; o; o >>= 1) {
            ps += __shfl_down_sync(0xffffffffu, ps, o, 16);
            pt += __shfl_down_sync(0xffffffffu, pt, o, 16);
        }
        if (leader) {
            g_ssrc[(node0 + n) * NH + h] = ps;
            g_stgt[(node0 + n) * NH + h] = pt;
            msrc = fmaxf(msrc, ps);
            mtgt = fmaxf(mtgt, pt);
        }
    }
    if (leader) {
        atomicMax(&g_maxsrc[h], f2u_ord(msrc));
        atomicMax(&g_maxtgt[h], f2u_ord(mtgt));
    }
}

// ---------------- CSR scan: coalesced smem staging + warp-shuffle scan ---------
__global__ void __launch_bounds__(1024) k_scan() {
    const int PER = 10;                 // 1024 * 10 >= NN
    __shared__ int cs[NN];              // 40 KB, coalesced staging
    __shared__ int wt[32];
    int t = threadIdx.x;

    for (int i = t; i < NN; i += 1024) cs[i] = g_count[i];   // coalesced, MLP=10
    __syncthreads();

    int base = t * PER;
    int loc[PER];
    int sum = 0;
#pragma unroll
    for (int i = 0; i < PER; i++) {
        int idx = base + i;
        int v = (idx < NN) ? cs[idx] : 0;
        loc[i] = sum;
        sum += v;
    }
    int lane = t & 31, w = t >> 5;
    int s = sum;
#pragma unroll
    for (int o = 1; o < 32; o <<= 1) {
        int y = __shfl_up_sync(0xffffffffu, s, o);
        if (lane >= o) s += y;
    }
    if (lane == 31) wt[w] = s;
    __syncthreads();
    if (w == 0) {
        int v = wt[lane];
        int s2 = v;
#pragma unroll
        for (int o = 1; o < 32; o <<= 1) {
            int y = __shfl_up_sync(0xffffffffu, s2, o);
            if (lane >= o) s2 += y;
        }
        wt[lane] = s2 - v;
    }
    __syncthreads();
    int off = (s - sum) + wt[w];
#pragma unroll
    for (int i = 0; i < PER; i++) {
        int idx = base + i;
        if (idx < NN) cs[idx] = off + loc[i];
    }
    __syncthreads();
    for (int i = t; i < NN; i += 1024) {   // coalesced write-out
        int o = cs[i];
        g_offs[i] = o;
        g_cursor[i] = o;
    }
    if (t == 1023) g_offs[NN] = off + sum;

    // softmax shift constants (upper bound of edge max; shift-invariant)
    if (t < NH) {
        float c = u2f_ord(g_maxsrc[t]) + u2f_ord(g_maxtgt[t]);
        g_C[t] = fmaxf(c, NEG * c);
    }
}

// ---------------- CSR scatter: src ids into segment order ----------------
__global__ void k_scatter(const int* __restrict__ edges) {
    int e = blockIdx.x * 256 + threadIdx.x;
    if (e < EE) {
        int p = atomicAdd(&g_cursor[edges[EE + e]], 1);
        g_ssorted[p] = edges[e];
    }
}

// ---------------- aggregation: block per node, inline softmax, float4 ----------
// Staging: 128 threads compute exp for 32 edges x 8 heads (all lanes packed).
// Compute: warp w handles edges w, w+4, ...; lane l owns features [4l, 4l+4)
// -> one LDG.128 per edge covers the full 512B proj row.
__global__ void __launch_bounds__(128) k_agg(float* __restrict__ out) {
    __shared__ int    src_s[32];
    __shared__ float  att_s[32][NH];
    __shared__ float4 red_s[4][32];
    __shared__ float  den_red[128];
    __shared__ float  stgt_s[NH], C_s[NH];

    int n = blockIdx.x, t = threadIdx.x;
    int lane = t & 31, w = t >> 5;

    if (t < NH) { stgt_s[t] = g_stgt[n * NH + t]; C_s[t] = g_C[t]; }
    if (t == 8) g_count[n] = 0;                  // re-zero for next replay
    if (n == 0 && t >= 16 && t < 24) g_maxsrc[t - 16] = 0u;
    if (n == 0 && t >= 24 && t < 32) g_maxtgt[t - 24] = 0u;
    __syncthreads();

    int start = g_offs[n], end = g_offs[n + 1];
    int hs = t & 7;                              // staging head
    float stgt_h = stgt_s[hs];
    float C_h = C_s[hs];
    float4 acc = make_float4(0.f, 0.f, 0.f, 0.f);
    float den_part = 0.f;
    int h4 = lane >> 2;                          // compute head (per feature group)

    for (int base = start; base < end; base += 32) {
        int m = min(32, end - base);
        __syncthreads();
        if (t < m) src_s[t] = g_ssorted[base + t];
        __syncthreads();
#pragma unroll
        for (int j = 0; j < 2; j++) {
            int slot = (t + j * 128) >> 3;
            if (slot < m) {
                float v = g_ssrc[src_s[slot] * NH + hs] + stgt_h;
                float ex = __expf(fmaxf(v, NEG * v) - C_h);
                att_s[slot][hs] = ex;
                den_part += ex;
            }
        }
        __syncthreads();
        int j = w;
        for (; j + 12 < m; j += 16) {            // 4 edges/iter -> MLP=4
            float a0 = att_s[j +  0][h4];
            float a1 = att_s[j +  4][h4];
            float a2 = att_s[j +  8][h4];
            float a3 = att_s[j + 12][h4];
            float4 p0 = ((const float4*)(g_proj + src_s[j +  0] * FIN))[lane];
            float4 p1 = ((const float4*)(g_proj + src_s[j +  4] * FIN))[lane];
            float4 p2 = ((const float4*)(g_proj + src_s[j +  8] * FIN))[lane];
            float4 p3 = ((const float4*)(g_proj + src_s[j + 12] * FIN))[lane];
            acc.x += a0 * p0.x; acc.y += a0 * p0.y; acc.z += a0 * p0.z; acc.w += a0 * p0.w;
            acc.x += a1 * p1.x; acc.y += a1 * p1.y; acc.z += a1 * p1.z; acc.w += a1 * p1.w;
            acc.x += a2 * p2.x; acc.y += a2 * p2.y; acc.z += a2 * p2.z; acc.w += a2 * p2.w;
            acc.x += a3 * p3.x; acc.y += a3 * p3.y; acc.z += a3 * p3.z; acc.w += a3 * p3.w;
        }
        for (; j < m; j += 4) {
            float a = att_s[j][h4];
            float4 p = ((const float4*)(g_proj + src_s[j] * FIN))[lane];
            acc.x += a * p.x; acc.y += a * p.y; acc.z += a * p.z; acc.w += a * p.w;
        }
    }

    red_s[w][lane] = acc;
    den_red[t] = den_part;
    __syncthreads();
    if (w == 0) {
        float4 a = red_s[0][lane];
#pragma unroll
        for (int ww = 1; ww < 4; ww++) {
            float4 b = red_s[ww][lane];
            a.x += b.x; a.y += b.y; a.z += b.z; a.w += b.w;
        }
        float den = 0.f;
        for (int k = h4; k < 128; k += 8) den += den_red[k];
        float inv = 1.0f / (den + EPSF);
        float4* o4 = (float4*)(out + n * FIN);
        float4 o = o4[lane];
        o.x += a.x * inv; o.y += a.y * inv; o.z += a.z * inv; o.w += a.w * inv;
        o4[lane] = o;
    }
}

// ---------------- launch ----------------
extern "C" void kernel_launch(void* const* d_in, const int* in_sizes, int n_in,
                              void* d_out, int out_size)
{
    const float* x     = (const float*)d_in[0];
    const int*   edges = (const int*)d_in[1];     // int32 (JAX x64 disabled)
    const float* Wp    = (const float*)d_in[2];
    const float* Ws    = (const float*)d_in[3];
    const float* s_src = (const float*)d_in[4];
    const float* s_tgt = (const float*)d_in[5];
    const float* bias  = (const float*)d_in[6];
    float* out = (float*)d_out;

    k_fused<<<GEMM_BLOCKS + COUNT_BLOCKS, 256>>>(x, Wp, Ws, bias, s_src, s_tgt, edges, out);
    k_scan<<<1, 1024>>>();
    k_scatter<<<(EE + 255) / 256, 256>>>(edges);
    k_agg<<<NN, 128>>>(out);
}